// round 7
// baseline (speedup 1.0000x reference)
#include <cuda_runtime.h>
#include <cuda_fp16.h>
#include <cstdint>

#define B_   4
#define S_   256
#define H_   768
#define NTOT 3840   // 5*768 : 4 basis slots + self slot
#define KW   1024   // 4*256 : step-2 K (4 c-blocks of 256)

// ---------------- static device scratch -------------------------------------
__device__ __align__(256) __half g_h[B_ * S_ * H_];      // hidden fp16
__device__ __align__(256) __half g_bas[4 * H_ * H_];     // basic fp16 [c][h][o]
__device__ __align__(256) __half g_selfnt[H_ * H_];      // selfw fp16 [o][h] (no transpose)
__device__ __align__(256) __half g_W[B_ * S_ * KW];      // W [b][i][c*256+j]
__device__ __align__(256) __half g_hb[B_ * S_ * NTOT];   // hb [b][s][n]
__device__ __align__(256) int    g_relsT[B_ * S_ * S_];  // rels transposed

// ---------------- helpers ---------------------------------------------------
__device__ __forceinline__ uint32_t s2u(const void* p) {
    uint32_t a;
    asm("{ .reg .u64 t; cvta.to.shared.u64 t, %1; cvt.u32.u64 %0, t; }"
        : "=r"(a) : "l"(p));
    return a;
}
__device__ __forceinline__ void cp16(uint32_t dst, const void* src) {
    asm volatile("cp.async.cg.shared.global [%0], [%1], 16;"
                 :: "r"(dst), "l"(src) : "memory");
}
__device__ __forceinline__ void ldsm4(uint32_t* r, uint32_t addr) {
    asm volatile("ldmatrix.sync.aligned.m8n8.x4.shared.b16 {%0,%1,%2,%3}, [%4];"
                 : "=r"(r[0]), "=r"(r[1]), "=r"(r[2]), "=r"(r[3]) : "r"(addr));
}
__device__ __forceinline__ void ldsm4t(uint32_t* r, uint32_t addr) {
    asm volatile("ldmatrix.sync.aligned.m8n8.x4.trans.shared.b16 {%0,%1,%2,%3}, [%4];"
                 : "=r"(r[0]), "=r"(r[1]), "=r"(r[2]), "=r"(r[3]) : "r"(addr));
}
__device__ __forceinline__ void mma_f16(float* d, const uint32_t* a,
                                        uint32_t b0, uint32_t b1) {
    asm volatile("mma.sync.aligned.m16n8k16.row.col.f32.f16.f16.f32 "
                 "{%0,%1,%2,%3}, {%4,%5,%6,%7}, {%8,%9}, {%0,%1,%2,%3};"
                 : "+f"(d[0]), "+f"(d[1]), "+f"(d[2]), "+f"(d[3])
                 : "r"(a[0]), "r"(a[1]), "r"(a[2]), "r"(a[3]), "r"(b0), "r"(b1));
}

// ---------------- SMEM layout ------------------------------------------------
// Row-major tiles (A and nt-B): rows of 64B (32 halves = one 32-K chunk),
// pitch 80 -> ldsm banks 20r mod 32 conflict-free.
// Trans-B: k-rows of NCOLS*2 B + 16B pad; pitch 272(128n)/144(64n):
// conflict-free trans ldsm.
#define A_PITCH 80

// Row-major tile loader: MROWS x 32 halves (used for A, and for nt-B).
template<int MROWS, int NTH>
__device__ __forceinline__ void ld_rows32(const __half* __restrict__ src, int ld,
                                          uint32_t s, int t) {
    #pragma unroll
    for (int u = 0; u < MROWS * 4 / NTH; u++) {
        const int id = t + NTH * u;
        const int r = id >> 2, seg = id & 3;
        cp16(s + r * A_PITCH + seg * 16, src + (size_t)r * ld + seg * 8);
    }
}
// Trans-B tile loader: 32 k-rows x NCOLS halves.
template<int NCOLS, int BP, int NTH>
__device__ __forceinline__ void ld_bt32(const __half* __restrict__ src, int ld,
                                        uint32_t s, int t) {
    #pragma unroll
    for (int u = 0; u < 32 * (NCOLS / 8) / NTH; u++) {
        const int id = t + NTH * u;
        const int k = id / (NCOLS / 8), q = id % (NCOLS / 8);
        cp16(s + k * BP + q * 16, src + (size_t)k * ld + q * 8);
    }
}

// One 16-K sub-chunk, trans-B. Warp tile 32 x (NG*16).
template<int BP, int NG>
__device__ __forceinline__ void sub_t(uint32_t a_s, uint32_t b_s,
                                      float acc[2][NG * 2][4],
                                      int lane, int wm, int wn)
{
    const int arow = wm * 32 + (lane & 15);
    const uint32_t abase = a_s + (uint32_t)arow * A_PITCH + (uint32_t)(lane >> 4) * 16;
    uint32_t ah[2][4], bh[NG][4];
    ldsm4(ah[0], abase);
    ldsm4(ah[1], abase + 16 * A_PITCH);
    const int krow = (lane & 7) | ((lane >> 1) & 8);
    const int noff = (lane & 8) ? 16 : 0;
    #pragma unroll
    for (int g = 0; g < NG; g++)
        ldsm4t(bh[g], b_s + (uint32_t)krow * BP + (uint32_t)(wn * (NG * 32) + g * 32) + noff);
    #pragma unroll
    for (int mt = 0; mt < 2; mt++)
        #pragma unroll
        for (int g = 0; g < NG; g++)
            #pragma unroll
            for (int s = 0; s < 2; s++)
                mma_f16(acc[mt][g * 2 + s], ah[mt], bh[g][s], bh[g][s + 2]);
}

// One 16-K sub-chunk, nt-B ([n][k] rows, R3-validated fragment mapping).
template<int NG>
__device__ __forceinline__ void sub_nt(uint32_t a_s, uint32_t b_s,
                                       float acc[2][NG * 2][4],
                                       int lane, int wm, int wn)
{
    const int arow = wm * 32 + (lane & 15);
    const uint32_t koff = (uint32_t)(lane >> 4) * 16;
    const uint32_t abase = a_s + (uint32_t)arow * A_PITCH + koff;
    uint32_t ah[2][4], bh[NG][4];
    ldsm4(ah[0], abase);
    ldsm4(ah[1], abase + 16 * A_PITCH);
    const int brow = wn * (NG * 16) + (lane & 15);
    #pragma unroll
    for (int g = 0; g < NG; g++)
        ldsm4(bh[g], b_s + (uint32_t)(brow + g * 16) * A_PITCH + koff);
    #pragma unroll
    for (int mt = 0; mt < 2; mt++)
        #pragma unroll
        for (int g = 0; g < NG; g++)
            #pragma unroll
            for (int s = 0; s < 2; s++)
                mma_f16(acc[mt][g * 2 + s], ah[mt], bh[g][s], bh[g][s + 2]);
}

// ---------------------------------------------------------------------------
// Fused prep: cvt hidden | cvt basic | cvt selfw | transpose rels. One launch.
// ---------------------------------------------------------------------------
#define NB_H    768     // 786432/1024
#define NB_BAS  2304    // 2359296/1024
#define NB_SELF 576     // 589824/1024
#define NB_RELS 256     // 4 * 64 tiles

__global__ __launch_bounds__(256) void prep_kernel(
    const float* __restrict__ hidden, const float* __restrict__ basic,
    const float* __restrict__ selfw, const int* __restrict__ rels)
{
    const int blk = blockIdx.x;
    const int t = threadIdx.x;
    if (blk < NB_H + NB_BAS + NB_SELF) {
        const float* src; __half* dst; int i;
        if (blk < NB_H) {
            src = hidden; dst = g_h; i = blk * 256 + t;
        } else if (blk < NB_H + NB_BAS) {
            src = basic; dst = g_bas; i = (blk - NB_H) * 256 + t;
        } else {
            src = selfw; dst = g_selfnt; i = (blk - NB_H - NB_BAS) * 256 + t;
        }
        float4 v = reinterpret_cast<const float4*>(src)[i];
        reinterpret_cast<__half2*>(dst)[i * 2]     = __floats2half2_rn(v.x, v.y);
        reinterpret_cast<__half2*>(dst)[i * 2 + 1] = __floats2half2_rn(v.z, v.w);
    } else {
        __shared__ int tile[32][33];
        const int id = blk - (NB_H + NB_BAS + NB_SELF);
        const int b = id >> 6, tl = id & 63;
        const int j0 = (tl & 7) * 32, i0 = (tl >> 3) * 32;
        const int tx = t & 31, ty = t >> 5;
        #pragma unroll
        for (int r = 0; r < 4; r++)
            tile[ty + 8 * r][tx] = rels[((size_t)b * S_ + i0 + ty + 8 * r) * S_ + j0 + tx];
        __syncthreads();
        #pragma unroll
        for (int r = 0; r < 4; r++)
            g_relsT[((size_t)b * S_ + j0 + ty + 8 * r) * S_ + i0 + tx] = tile[tx][ty + 8 * r];
    }
}

// ---------------------------------------------------------------------------
// build_w: histogram + W[b][i][c*256+j] fp16. All reads coalesced.
// ---------------------------------------------------------------------------
__global__ void build_w_kernel(const int* __restrict__ rels,
                               const float* __restrict__ rel_weight) {
    const int bi = blockIdx.x;
    const int b = bi >> 8;
    const int i = bi & 255;
    const int t = threadIdx.x;

    __shared__ int   cf[32], cr[32];
    __shared__ float inv_f[32], inv_r[32];
    __shared__ float rw[64 * 4];

    if (t < 32) { cf[t] = 0; cr[t] = 0; }
    rw[t] = rel_weight[t];
    __syncthreads();

    const int lf = rels[(b * S_ + i) * S_ + t];
    const int lr = g_relsT[(b * S_ + i) * S_ + t];
    if (lf > 0) atomicAdd(&cf[lf], 1);
    if (lr > 0) atomicAdd(&cr[lr], 1);
    __syncthreads();

    if (t < 32) {
        inv_f[t] = 1.0f / (float)(cf[t] > 0 ? cf[t] : 1);
        inv_r[t] = 1.0f / (float)(cr[t] > 0 ? cr[t] : 1);
    }
    __syncthreads();

    float w[4] = {0.f, 0.f, 0.f, 0.f};
    if (lf > 0) {
        const float s = inv_f[lf];
        #pragma unroll
        for (int c = 0; c < 4; c++) w[c] += rw[lf * 4 + c] * s;
    }
    if (lr > 0) {
        const float s = inv_r[lr];
        #pragma unroll
        for (int c = 0; c < 4; c++) w[c] += rw[(lr + 32) * 4 + c] * s;
    }
    #pragma unroll
    for (int c = 0; c < 4; c++)
        g_W[((size_t)(b * S_ + i)) * KW + c * 256 + t] = __float2half(w[c]);
}

// ---------------------------------------------------------------------------
// GEMM-HB: hb[b] (256x3840) = hidden[b] (256x768) @ [basic (trans-B) |
// selfw (nt-B)] ; grid (30, 2, 4), 256 thr, CTA 128x128, warp 32x64.
// 3-stage cp.async, K-chunk 32 (NC=24).
// ---------------------------------------------------------------------------
#define HB_BP   272
#define HB_ABUF (128 * A_PITCH)                // 10240
#define HB_BREG (128 * A_PITCH)                // max(trans 8704, nt 10240)
#define HB_STG  (HB_ABUF + HB_BREG)            // 20480
#define HB_SMEM (3 * HB_STG)                   // 61440

__global__ __launch_bounds__(256, 2) void gemm_hb_kernel() {
    extern __shared__ __align__(128) char sm[];
    const int n0 = blockIdx.x * 128;     // never straddles a 768-slot
    const int m0 = blockIdx.y * 128;
    const int b  = blockIdx.z;
    const int cslot = n0 / 768;
    const int o0 = n0 - cslot * 768;
    const bool nt = (cslot == 4);

    const __half* A  = g_h + ((size_t)(b * S_ + m0)) * H_;
    const __half* Bt = g_bas + (size_t)cslot * H_ * H_ + o0;   // trans: [k][n]
    const __half* Bn = g_selfnt + (size_t)o0 * H_;             // nt:    [n][k]

    const int t = threadIdx.x, lane = t & 31, wid = t >> 5;
    const int wm = wid & 3, wn = wid >> 2;
    const uint32_t smb = s2u(sm);

    float acc[2][8][4] = {};
    const int NC = 24;
    #pragma unroll 1
    for (int p = 0; p < 2; p++) {   // prologue: stages 0,1
        const int k0 = p * 32;
        const uint32_t st = smb + (uint32_t)p * HB_STG;
        ld_rows32<128, 256>(A + k0, H_, st, t);
        if (!nt) ld_bt32<128, HB_BP, 256>(Bt + (size_t)k0 * H_, H_, st + HB_ABUF, t);
        else     ld_rows32<128, 256>(Bn + k0, H_, st + HB_ABUF, t);
        asm volatile("cp.async.commit_group;" ::: "memory");
    }
    for (int c = 0; c < NC; c++) {
        asm volatile("cp.async.wait_group 1;" ::: "memory");
        __syncthreads();
        const uint32_t st = smb + (uint32_t)(c % 3) * HB_STG;
        if (!nt) {
            sub_t<HB_BP, 4>(st, st + HB_ABUF, acc, lane, wm, wn);
            sub_t<HB_BP, 4>(st + 32, st + HB_ABUF + 16 * HB_BP, acc, lane, wm, wn);
        } else {
            sub_nt<4>(st, st + HB_ABUF, acc, lane, wm, wn);
            sub_nt<4>(st + 32, st + HB_ABUF + 32, acc, lane, wm, wn);
        }
        if (c + 2 < NC) {
            const int k0 = (c + 2) * 32;
            const uint32_t sn = smb + (uint32_t)((c + 2) % 3) * HB_STG;
            ld_rows32<128, 256>(A + k0, H_, sn, t);
            if (!nt) ld_bt32<128, HB_BP, 256>(Bt + (size_t)k0 * H_, H_, sn + HB_ABUF, t);
            else     ld_rows32<128, 256>(Bn + k0, H_, sn + HB_ABUF, t);
        }
        asm volatile("cp.async.commit_group;" ::: "memory");
    }

    #pragma unroll
    for (int mt = 0; mt < 2; mt++)
        #pragma unroll
        for (int nv = 0; nv < 8; nv++) {
            const int row = m0 + wm * 32 + mt * 16 + (lane >> 2);
            const int col = n0 + wn * 64 + nv * 8 + (lane & 3) * 2;
            *reinterpret_cast<__half2*>(g_hb + (size_t)(b * S_ + row) * NTOT + col) =
                __floats2half2_rn(acc[mt][nv][0], acc[mt][nv][1]);
            *reinterpret_cast<__half2*>(g_hb + (size_t)(b * S_ + row + 8) * NTOT + col) =
                __floats2half2_rn(acc[mt][nv][2], acc[mt][nv][3]);
        }
}

// ---------------------------------------------------------------------------
// GEMM-OUT: out[b] (256x768) = W[b] (256x1024) @ hb_stack (1024x768) + self
// grid (12, 4, 4), 128 thr, CTA 64x64, warp 32x32. 3-stage, K-chunk 32.
// ---------------------------------------------------------------------------
#define OUT_BP   144
#define OUT_ABUF (64 * A_PITCH)                // 5120
#define OUT_BBUF (32 * OUT_BP)                 // 4608
#define OUT_STG  (OUT_ABUF + OUT_BBUF)         // 9728

__global__ __launch_bounds__(128, 3) void gemm_out_kernel(float* __restrict__ out) {
    __shared__ __align__(128) char sm[3 * OUT_STG];
    const int n0 = blockIdx.x * 64;
    const int m0 = blockIdx.y * 64;
    const int b  = blockIdx.z;

    const __half* A  = g_W + ((size_t)(b * S_ + m0)) * KW;
    const __half* hb = g_hb + (size_t)b * S_ * NTOT + n0;

    const int t = threadIdx.x, lane = t & 31, wid = t >> 5;
    const int wm = wid & 1, wn = wid >> 1;
    const uint32_t smb = s2u(sm);

    float acc[2][4][4] = {};
    const int NC = 32;
    // B row k=(cb*256+j) -> hb[b][j][cb*768+n]; chunk of 32 never straddles.
    #pragma unroll 1
    for (int p = 0; p < 2; p++) {
        const int k0 = p * 32;
        const size_t boff = (size_t)(k0 >> 8) * 768 + (size_t)(k0 & 255) * NTOT;
        const uint32_t st = smb + (uint32_t)p * OUT_STG;
        ld_rows32<64, 128>(A + k0, KW, st, t);
        ld_bt32<64, OUT_BP, 128>(hb + boff, NTOT, st + OUT_ABUF, t);
        asm volatile("cp.async.commit_group;" ::: "memory");
    }
    for (int c = 0; c < NC; c++) {
        asm volatile("cp.async.wait_group 1;" ::: "memory");
        __syncthreads();
        const uint32_t st = smb + (uint32_t)(c % 3) * OUT_STG;
        sub_t<OUT_BP, 2>(st, st + OUT_ABUF, acc, lane, wm, wn);
        sub_t<OUT_BP, 2>(st + 32, st + OUT_ABUF + 16 * OUT_BP, acc, lane, wm, wn);
        if (c + 2 < NC) {
            const int k0 = (c + 2) * 32;
            const size_t boff = (size_t)(k0 >> 8) * 768 + (size_t)(k0 & 255) * NTOT;
            const uint32_t sn = smb + (uint32_t)((c + 2) % 3) * OUT_STG;
            ld_rows32<64, 128>(A + k0, KW, sn, t);
            ld_bt32<64, OUT_BP, 128>(hb + boff, NTOT, sn + OUT_ABUF, t);
        }
        asm volatile("cp.async.commit_group;" ::: "memory");
    }

    // epilogue: add self slot (hb[:, 3072+n]) and store fp32
    #pragma unroll
    for (int mt = 0; mt < 2; mt++)
        #pragma unroll
        for (int nv = 0; nv < 4; nv++) {
            const int row = m0 + wm * 32 + mt * 16 + (lane >> 2);
            const int col = n0 + wn * 32 + nv * 8 + (lane & 3) * 2;
            #pragma unroll
            for (int hf = 0; hf < 2; hf++) {
                const int r = row + hf * 8;
                __half2 sh = *reinterpret_cast<const __half2*>(
                    g_hb + (size_t)(b * S_ + r) * NTOT + 3072 + col);
                float2 v;
                v.x = acc[mt][nv][hf * 2 + 0] + __half2float(sh.x);
                v.y = acc[mt][nv][hf * 2 + 1] + __half2float(sh.y);
                *reinterpret_cast<float2*>(out + (size_t)(b * S_ + r) * H_ + col) = v;
            }
        }
}

// ---------------------------------------------------------------------------
extern "C" void kernel_launch(void* const* d_in, const int* in_sizes, int n_in,
                              void* d_out, int out_size) {
    const float* hidden     = (const float*)d_in[0]; // [4,256,768]
    const int*   rels       = (const int*)  d_in[1]; // [4,256,256]
    const float* basic      = (const float*)d_in[2]; // [4,768,768]
    const float* rel_weight = (const float*)d_in[3]; // [64,4]
    const float* self_w     = (const float*)d_in[4]; // [768,768] (out,in)
    float* out = (float*)d_out;                      // [4,256,768]

    cudaFuncSetAttribute(gemm_hb_kernel,
                         cudaFuncAttributeMaxDynamicSharedMemorySize, HB_SMEM);

    prep_kernel<<<NB_H + NB_BAS + NB_SELF + NB_RELS, 256>>>(hidden, basic, self_w, rels);
    build_w_kernel<<<B_ * S_, 256>>>(rels, rel_weight);
    gemm_hb_kernel<<<dim3(NTOT / 128, S_ / 128, B_), 256, HB_SMEM>>>();
    gemm_out_kernel<<<dim3(H_ / 64, S_ / 64, B_), 128>>>(out);
}

// round 8
// speedup vs baseline: 1.1154x; 1.1154x over previous
#include <cuda_runtime.h>
#include <cuda_fp16.h>
#include <cstdint>

#define B_   4
#define S_   256
#define H_   768
#define NTOT 3840   // 5*768 : 4 basis slots + self slot
#define KW   1024   // 4*256 : step-2 K (4 c-blocks of 256)

// ---------------- static device scratch -------------------------------------
__device__ __align__(256) __half g_h[B_ * S_ * H_];      // hidden fp16
__device__ __align__(256) __half g_bas[4 * H_ * H_];     // basic fp16 [c][h][o]
__device__ __align__(256) __half g_self[H_ * H_];        // selfw^T fp16 [h][o]
__device__ __align__(256) __half g_W[B_ * S_ * KW];      // W [b][i][c*256+j]
__device__ __align__(256) __half g_hb[B_ * S_ * NTOT];   // hb [b][s][n]
__device__ __align__(256) int    g_relsT[B_ * S_ * S_];  // rels transposed
__device__ __align__(256) float  g_part[4 * B_ * S_ * H_]; // split-K partials

// ---------------- helpers ---------------------------------------------------
__device__ __forceinline__ uint32_t s2u(const void* p) {
    uint32_t a;
    asm("{ .reg .u64 t; cvta.to.shared.u64 t, %1; cvt.u32.u64 %0, t; }"
        : "=r"(a) : "l"(p));
    return a;
}
__device__ __forceinline__ void cp16(uint32_t dst, const void* src) {
    asm volatile("cp.async.cg.shared.global [%0], [%1], 16;"
                 :: "r"(dst), "l"(src) : "memory");
}
__device__ __forceinline__ void ldsm4(uint32_t* r, uint32_t addr) {
    asm volatile("ldmatrix.sync.aligned.m8n8.x4.shared.b16 {%0,%1,%2,%3}, [%4];"
                 : "=r"(r[0]), "=r"(r[1]), "=r"(r[2]), "=r"(r[3]) : "r"(addr));
}
__device__ __forceinline__ void ldsm4t(uint32_t* r, uint32_t addr) {
    asm volatile("ldmatrix.sync.aligned.m8n8.x4.trans.shared.b16 {%0,%1,%2,%3}, [%4];"
                 : "=r"(r[0]), "=r"(r[1]), "=r"(r[2]), "=r"(r[3]) : "r"(addr));
}
__device__ __forceinline__ void mma_f16(float* d, const uint32_t* a,
                                        uint32_t b0, uint32_t b1) {
    asm volatile("mma.sync.aligned.m16n8k16.row.col.f32.f16.f16.f32 "
                 "{%0,%1,%2,%3}, {%4,%5,%6,%7}, {%8,%9}, {%0,%1,%2,%3};"
                 : "+f"(d[0]), "+f"(d[1]), "+f"(d[2]), "+f"(d[3])
                 : "r"(a[0]), "r"(a[1]), "r"(a[2]), "r"(a[3]), "r"(b0), "r"(b1));
}

// ---------------- SMEM layout ------------------------------------------------
// A: rows of 64B (32 halves, one 32-K chunk), pitch 80 -> conflict-free ldsm.
// B: k-rows of NCOLS*2 B + 16B pad; pitch 272(128n)/144(64n): conflict-free
// trans ldsm.
#define A_PITCH 80

template<int MROWS, int NTH>
__device__ __forceinline__ void ld_rows32(const __half* __restrict__ src, int ld,
                                          uint32_t s, int t) {
    #pragma unroll
    for (int u = 0; u < MROWS * 4 / NTH; u++) {
        const int id = t + NTH * u;
        const int r = id >> 2, seg = id & 3;
        cp16(s + r * A_PITCH + seg * 16, src + (size_t)r * ld + seg * 8);
    }
}
template<int NCOLS, int BP, int NTH>
__device__ __forceinline__ void ld_bt32(const __half* __restrict__ src, int ld,
                                        uint32_t s, int t) {
    #pragma unroll
    for (int u = 0; u < 32 * (NCOLS / 8) / NTH; u++) {
        const int id = t + NTH * u;
        const int k = id / (NCOLS / 8), q = id % (NCOLS / 8);
        cp16(s + k * BP + q * 16, src + (size_t)k * ld + q * 8);
    }
}

// One 16-K sub-chunk, trans-B. Warp tile 32 x (NG*16).
template<int BP, int NG>
__device__ __forceinline__ void sub_t(uint32_t a_s, uint32_t b_s,
                                      float acc[2][NG * 2][4],
                                      int lane, int wm, int wn)
{
    const int arow = wm * 32 + (lane & 15);
    const uint32_t abase = a_s + (uint32_t)arow * A_PITCH + (uint32_t)(lane >> 4) * 16;
    uint32_t ah[2][4], bh[NG][4];
    ldsm4(ah[0], abase);
    ldsm4(ah[1], abase + 16 * A_PITCH);
    const int krow = (lane & 7) | ((lane >> 1) & 8);
    const int noff = (lane & 8) ? 16 : 0;
    #pragma unroll
    for (int g = 0; g < NG; g++)
        ldsm4t(bh[g], b_s + (uint32_t)krow * BP + (uint32_t)(wn * (NG * 32) + g * 32) + noff);
    #pragma unroll
    for (int mt = 0; mt < 2; mt++)
        #pragma unroll
        for (int g = 0; g < NG; g++)
            #pragma unroll
            for (int s = 0; s < 2; s++)
                mma_f16(acc[mt][g * 2 + s], ah[mt], bh[g][s], bh[g][s + 2]);
}

// ---------------------------------------------------------------------------
// Fused prep: cvt hidden | cvt basic | transpose selfw | transpose rels.
// ---------------------------------------------------------------------------
#define NB_H    768     // 786432/1024
#define NB_BAS  2304    // 2359296/1024
#define NB_SELF 576     // 24x24 32x32-tiles
#define NB_RELS 256     // 4 * 64 tiles

__global__ __launch_bounds__(256) void prep_kernel(
    const float* __restrict__ hidden, const float* __restrict__ basic,
    const float* __restrict__ selfw, const int* __restrict__ rels)
{
    const int blk = blockIdx.x;
    const int t = threadIdx.x;
    if (blk < NB_H + NB_BAS) {
        const float* src; __half* dst; int i;
        if (blk < NB_H) { src = hidden; dst = g_h; i = blk * 256 + t; }
        else            { src = basic;  dst = g_bas; i = (blk - NB_H) * 256 + t; }
        float4 v = reinterpret_cast<const float4*>(src)[i];
        reinterpret_cast<__half2*>(dst)[i * 2]     = __floats2half2_rn(v.x, v.y);
        reinterpret_cast<__half2*>(dst)[i * 2 + 1] = __floats2half2_rn(v.z, v.w);
    } else if (blk < NB_H + NB_BAS + NB_SELF) {
        __shared__ float tile[32][33];
        const int tl = blk - (NB_H + NB_BAS);
        const int h0 = (tl % 24) * 32, o0 = (tl / 24) * 32;
        const int tx = t & 31, ty = t >> 5;
        #pragma unroll
        for (int r = 0; r < 4; r++)
            tile[ty + 8 * r][tx] = selfw[(size_t)(o0 + ty + 8 * r) * H_ + h0 + tx];
        __syncthreads();
        #pragma unroll
        for (int r = 0; r < 4; r++)
            g_self[(size_t)(h0 + ty + 8 * r) * H_ + o0 + tx] =
                __float2half(tile[tx][ty + 8 * r]);
    } else {
        __shared__ int tile[32][33];
        const int id = blk - (NB_H + NB_BAS + NB_SELF);
        const int b = id >> 6, tl = id & 63;
        const int j0 = (tl & 7) * 32, i0 = (tl >> 3) * 32;
        const int tx = t & 31, ty = t >> 5;
        #pragma unroll
        for (int r = 0; r < 4; r++)
            tile[ty + 8 * r][tx] = rels[((size_t)b * S_ + i0 + ty + 8 * r) * S_ + j0 + tx];
        __syncthreads();
        #pragma unroll
        for (int r = 0; r < 4; r++)
            g_relsT[((size_t)b * S_ + j0 + ty + 8 * r) * S_ + i0 + tx] = tile[tx][ty + 8 * r];
    }
}

// ---------------------------------------------------------------------------
// build_w: histogram + W[b][i][c*256+j] fp16. All reads coalesced.
// ---------------------------------------------------------------------------
__global__ void build_w_kernel(const int* __restrict__ rels,
                               const float* __restrict__ rel_weight) {
    const int bi = blockIdx.x;
    const int b = bi >> 8;
    const int i = bi & 255;
    const int t = threadIdx.x;

    __shared__ int   cf[32], cr[32];
    __shared__ float inv_f[32], inv_r[32];
    __shared__ float rw[64 * 4];

    if (t < 32) { cf[t] = 0; cr[t] = 0; }
    rw[t] = rel_weight[t];
    __syncthreads();

    const int lf = rels[(b * S_ + i) * S_ + t];
    const int lr = g_relsT[(b * S_ + i) * S_ + t];
    if (lf > 0) atomicAdd(&cf[lf], 1);
    if (lr > 0) atomicAdd(&cr[lr], 1);
    __syncthreads();

    if (t < 32) {
        inv_f[t] = 1.0f / (float)(cf[t] > 0 ? cf[t] : 1);
        inv_r[t] = 1.0f / (float)(cr[t] > 0 ? cr[t] : 1);
    }
    __syncthreads();

    float w[4] = {0.f, 0.f, 0.f, 0.f};
    if (lf > 0) {
        const float s = inv_f[lf];
        #pragma unroll
        for (int c = 0; c < 4; c++) w[c] += rw[lf * 4 + c] * s;
    }
    if (lr > 0) {
        const float s = inv_r[lr];
        #pragma unroll
        for (int c = 0; c < 4; c++) w[c] += rw[(lr + 32) * 4 + c] * s;
    }
    #pragma unroll
    for (int c = 0; c < 4; c++)
        g_W[((size_t)(b * S_ + i)) * KW + c * 256 + t] = __float2half(w[c]);
}

// ---------------------------------------------------------------------------
// GEMM-HB: hb[b] (256x3840) = hidden[b] (256x768) @ [basic|selfT] (768x3840)
// grid (30, 2, 4) = 240 CTAs, 256 thr, CTA 128x128, warp 32x64.
// 3-stage cp.async, K-chunk 32 (NC=24). Single trans-B path.
// ---------------------------------------------------------------------------
#define HB_BP   272
#define HB_ABUF (128 * A_PITCH)                // 10240
#define HB_BBUF (32 * HB_BP)                   // 8704
#define HB_STG  (HB_ABUF + HB_BBUF)            // 18944
#define HB_SMEM (3 * HB_STG)                   // 56832

__global__ __launch_bounds__(256, 2) void gemm_hb_kernel() {
    extern __shared__ __align__(128) char sm[];
    const int n0 = blockIdx.x * 128;     // never straddles a 768-slot
    const int m0 = blockIdx.y * 128;
    const int b  = blockIdx.z;
    const int cslot = n0 / 768;
    const int o0 = n0 - cslot * 768;

    const __half* A  = g_h + ((size_t)(b * S_ + m0)) * H_;
    const __half* Bm = (cslot < 4) ? g_bas + (size_t)cslot * H_ * H_ + o0
                                   : g_self + o0;

    const int t = threadIdx.x, lane = t & 31, wid = t >> 5;
    const int wm = wid & 3, wn = wid >> 2;
    const uint32_t smb = s2u(sm);

    float acc[2][8][4] = {};
    const int NC = 24;
    #pragma unroll 1
    for (int p = 0; p < 2; p++) {
        const int k0 = p * 32;
        const uint32_t st = smb + (uint32_t)p * HB_STG;
        ld_rows32<128, 256>(A + k0, H_, st, t);
        ld_bt32<128, HB_BP, 256>(Bm + (size_t)k0 * H_, H_, st + HB_ABUF, t);
        asm volatile("cp.async.commit_group;" ::: "memory");
    }
    for (int c = 0; c < NC; c++) {
        asm volatile("cp.async.wait_group 1;" ::: "memory");
        __syncthreads();
        const uint32_t st = smb + (uint32_t)(c % 3) * HB_STG;
        sub_t<HB_BP, 4>(st, st + HB_ABUF, acc, lane, wm, wn);
        sub_t<HB_BP, 4>(st + 32, st + HB_ABUF + 16 * HB_BP, acc, lane, wm, wn);
        if (c + 2 < NC) {
            const int k0 = (c + 2) * 32;
            const uint32_t sn = smb + (uint32_t)((c + 2) % 3) * HB_STG;
            ld_rows32<128, 256>(A + k0, H_, sn, t);
            ld_bt32<128, HB_BP, 256>(Bm + (size_t)k0 * H_, H_, sn + HB_ABUF, t);
        }
        asm volatile("cp.async.commit_group;" ::: "memory");
    }

    #pragma unroll
    for (int mt = 0; mt < 2; mt++)
        #pragma unroll
        for (int nv = 0; nv < 8; nv++) {
            const int row = m0 + wm * 32 + mt * 16 + (lane >> 2);
            const int col = n0 + wn * 64 + nv * 8 + (lane & 3) * 2;
            *reinterpret_cast<__half2*>(g_hb + (size_t)(b * S_ + row) * NTOT + col) =
                __floats2half2_rn(acc[mt][nv][0], acc[mt][nv][1]);
            *reinterpret_cast<__half2*>(g_hb + (size_t)(b * S_ + row + 8) * NTOT + col) =
                __floats2half2_rn(acc[mt][nv][2], acc[mt][nv][3]);
        }
}

// ---------------------------------------------------------------------------
// GEMM-OUT split-K: part[kc][row0..][n0..] = W[b][:,kc*256:+256] @ hb-block
// grid (12, 16, 4) = 768 CTAs, 128 thr, CTA 64x64, warp 32x32, K=256 (NC=8).
// ---------------------------------------------------------------------------
#define OUT_BP   144
#define OUT_ABUF (64 * A_PITCH)                // 5120
#define OUT_BBUF (32 * OUT_BP)                 // 4608
#define OUT_STG  (OUT_ABUF + OUT_BBUF)         // 9728

__global__ __launch_bounds__(128, 3) void gemm_out_kernel() {
    __shared__ __align__(128) char sm[3 * OUT_STG];
    const int n0 = blockIdx.x * 64;
    const int row0 = blockIdx.y * 64;        // 0..1024, within one batch
    const int kc = blockIdx.z;
    const int b = row0 >> 8;

    const __half* A  = g_W + (size_t)row0 * KW + kc * 256;
    const __half* Bm = g_hb + (size_t)b * S_ * NTOT + kc * 768 + n0;  // [j][...]

    const int t = threadIdx.x, lane = t & 31, wid = t >> 5;
    const int wm = wid & 1, wn = wid >> 1;
    const uint32_t smb = s2u(sm);

    float acc[2][4][4] = {};
    const int NC = 8;
    #pragma unroll 1
    for (int p = 0; p < 2; p++) {
        const int k0 = p * 32;
        const uint32_t st = smb + (uint32_t)p * OUT_STG;
        ld_rows32<64, 128>(A + k0, KW, st, t);
        ld_bt32<64, OUT_BP, 128>(Bm + (size_t)k0 * NTOT, NTOT, st + OUT_ABUF, t);
        asm volatile("cp.async.commit_group;" ::: "memory");
    }
    for (int c = 0; c < NC; c++) {
        asm volatile("cp.async.wait_group 1;" ::: "memory");
        __syncthreads();
        const uint32_t st = smb + (uint32_t)(c % 3) * OUT_STG;
        sub_t<OUT_BP, 2>(st, st + OUT_ABUF, acc, lane, wm, wn);
        sub_t<OUT_BP, 2>(st + 32, st + OUT_ABUF + 16 * OUT_BP, acc, lane, wm, wn);
        if (c + 2 < NC) {
            const int k0 = (c + 2) * 32;
            const uint32_t sn = smb + (uint32_t)((c + 2) % 3) * OUT_STG;
            ld_rows32<64, 128>(A + k0, KW, sn, t);
            ld_bt32<64, OUT_BP, 128>(Bm + (size_t)k0 * NTOT, NTOT, sn + OUT_ABUF, t);
        }
        asm volatile("cp.async.commit_group;" ::: "memory");
    }

    float* part = g_part + (size_t)kc * (B_ * S_ * H_);
    #pragma unroll
    for (int mt = 0; mt < 2; mt++)
        #pragma unroll
        for (int nv = 0; nv < 4; nv++) {
            const int row = row0 + wm * 32 + mt * 16 + (lane >> 2);
            const int col = n0 + wn * 32 + nv * 8 + (lane & 3) * 2;
            float2 v0, v1;
            v0.x = acc[mt][nv][0]; v0.y = acc[mt][nv][1];
            v1.x = acc[mt][nv][2]; v1.y = acc[mt][nv][3];
            *reinterpret_cast<float2*>(part + (size_t)row * H_ + col) = v0;
            *reinterpret_cast<float2*>(part + (size_t)(row + 8) * H_ + col) = v1;
        }
}

// ---------------------------------------------------------------------------
// Reduce: out = p0+p1+p2+p3 + self_slot(hb[:,3072+n]). 768 blocks x 256 thr.
// ---------------------------------------------------------------------------
__global__ __launch_bounds__(256) void reduce_kernel(float* __restrict__ out) {
    const int i = blockIdx.x * 256 + threadIdx.x;   // float4 index
    const int row = (i * 4) / H_;
    const int col = (i * 4) % H_;
    float4 s = reinterpret_cast<const float4*>(g_part)[i];
    #pragma unroll
    for (int kc = 1; kc < 4; kc++) {
        float4 p = reinterpret_cast<const float4*>(g_part + (size_t)kc * (B_ * S_ * H_))[i];
        s.x += p.x; s.y += p.y; s.z += p.z; s.w += p.w;
    }
    const __half2* sh = reinterpret_cast<const __half2*>(
        g_hb + (size_t)row * NTOT + 3072 + col);
    float2 a = __half22float2(sh[0]);
    float2 bv = __half22float2(sh[1]);
    s.x += a.x; s.y += a.y; s.z += bv.x; s.w += bv.y;
    reinterpret_cast<float4*>(out)[i] = s;
}

// ---------------------------------------------------------------------------
extern "C" void kernel_launch(void* const* d_in, const int* in_sizes, int n_in,
                              void* d_out, int out_size) {
    const float* hidden     = (const float*)d_in[0]; // [4,256,768]
    const int*   rels       = (const int*)  d_in[1]; // [4,256,256]
    const float* basic      = (const float*)d_in[2]; // [4,768,768]
    const float* rel_weight = (const float*)d_in[3]; // [64,4]
    const float* self_w     = (const float*)d_in[4]; // [768,768] (out,in)
    float* out = (float*)d_out;                      // [4,256,768]

    cudaFuncSetAttribute(gemm_hb_kernel,
                         cudaFuncAttributeMaxDynamicSharedMemorySize, HB_SMEM);

    prep_kernel<<<NB_H + NB_BAS + NB_SELF + NB_RELS, 256>>>(hidden, basic, self_w, rels);
    build_w_kernel<<<B_ * S_, 256>>>(rels, rel_weight);
    gemm_hb_kernel<<<dim3(NTOT / 128, S_ / 128, B_), 256, HB_SMEM>>>();
    gemm_out_kernel<<<dim3(H_ / 64, (B_ * S_) / 64, 4), 128>>>();
    reduce_kernel<<<(B_ * S_ * H_) / 4 / 256, 256>>>(out);
}

// round 9
// speedup vs baseline: 1.1241x; 1.0078x over previous
#include <cuda_runtime.h>
#include <cuda_fp16.h>
#include <cstdint>

#define B_   4
#define S_   256
#define H_   768
#define NTOT 3840   // 5*768 : 4 basis slots + self slot
#define KW   1024   // 4*256 : step-2 K (4 c-blocks of 256)

// ---------------- static device scratch -------------------------------------
__device__ __align__(256) __half g_h[B_ * S_ * H_];      // hidden fp16 [1024][768]
__device__ __align__(256) __half g_bas[4 * H_ * H_];     // basic fp16 [c][h][o]
__device__ __align__(256) __half g_self[H_ * H_];        // selfw^T fp16 [h][o]
__device__ __align__(256) __half g_W[B_ * S_ * KW];      // W [b][i][c*256+j]
__device__ __align__(256) __half g_hb[B_ * S_ * NTOT];   // hb [b][s][n]
__device__ __align__(256) int    g_relsT[B_ * S_ * S_];  // rels transposed
__device__ __align__(256) float  g_part[4 * B_ * S_ * H_]; // split-K partials

// ---------------- helpers ---------------------------------------------------
__device__ __forceinline__ uint32_t s2u(const void* p) {
    uint32_t a;
    asm("{ .reg .u64 t; cvta.to.shared.u64 t, %1; cvt.u32.u64 %0, t; }"
        : "=r"(a) : "l"(p));
    return a;
}
__device__ __forceinline__ void cp16(uint32_t dst, const void* src) {
    asm volatile("cp.async.cg.shared.global [%0], [%1], 16;"
                 :: "r"(dst), "l"(src) : "memory");
}
__device__ __forceinline__ void ldsm4(uint32_t* r, uint32_t addr) {
    asm volatile("ldmatrix.sync.aligned.m8n8.x4.shared.b16 {%0,%1,%2,%3}, [%4];"
                 : "=r"(r[0]), "=r"(r[1]), "=r"(r[2]), "=r"(r[3]) : "r"(addr));
}
__device__ __forceinline__ void ldsm4t(uint32_t* r, uint32_t addr) {
    asm volatile("ldmatrix.sync.aligned.m8n8.x4.trans.shared.b16 {%0,%1,%2,%3}, [%4];"
                 : "=r"(r[0]), "=r"(r[1]), "=r"(r[2]), "=r"(r[3]) : "r"(addr));
}
__device__ __forceinline__ void mma_f16(float* d, const uint32_t* a,
                                        uint32_t b0, uint32_t b1) {
    asm volatile("mma.sync.aligned.m16n8k16.row.col.f32.f16.f16.f32 "
                 "{%0,%1,%2,%3}, {%4,%5,%6,%7}, {%8,%9}, {%0,%1,%2,%3};"
                 : "+f"(d[0]), "+f"(d[1]), "+f"(d[2]), "+f"(d[3])
                 : "r"(a[0]), "r"(a[1]), "r"(a[2]), "r"(a[3]), "r"(b0), "r"(b1));
}

// ---------------- unified GEMM geometry --------------------------------------
// CTA tile 64(M) x 128(N), 128 threads = 4 warps, warp tile 32x64 (NG=4).
// K-chunk 32, 3-stage cp.async.
// A: rows of 64B (32 halves), pitch 80 -> conflict-free ldsm.
// B: 32 k-rows of 256B + 16B pad (pitch 272) -> conflict-free trans ldsm.
#define A_PITCH 80
#define G_BP    272
#define G_ABUF  (64 * A_PITCH)              // 5120
#define G_BBUF  (32 * G_BP)                 // 8704
#define G_STG   (G_ABUF + G_BBUF)           // 13824

__device__ __forceinline__ void ld_a32(const __half* __restrict__ src, int ld,
                                       uint32_t s, int t) {
    #pragma unroll
    for (int u = 0; u < 2; u++) {
        const int id = t + 128 * u;
        const int r = id >> 2, seg = id & 3;
        cp16(s + r * A_PITCH + seg * 16, src + (size_t)r * ld + seg * 8);
    }
}
__device__ __forceinline__ void ld_b32(const __half* __restrict__ src, int ld,
                                       uint32_t s, int t) {
    #pragma unroll
    for (int u = 0; u < 4; u++) {
        const int id = t + 128 * u;
        const int k = id >> 4, q = id & 15;
        cp16(s + k * G_BP + q * 16, src + (size_t)k * ld + q * 8);
    }
}

// One 16-K sub-chunk. wm in {0,1}, wn in {0,1}; NG=4 (64 n per warp).
__device__ __forceinline__ void sub_t4(uint32_t a_s, uint32_t b_s,
                                       float acc[2][8][4],
                                       int lane, int wm, int wn)
{
    const int arow = wm * 32 + (lane & 15);
    const uint32_t abase = a_s + (uint32_t)arow * A_PITCH + (uint32_t)(lane >> 4) * 16;
    uint32_t ah[2][4], bh[4][4];
    ldsm4(ah[0], abase);
    ldsm4(ah[1], abase + 16 * A_PITCH);
    const int krow = (lane & 7) | ((lane >> 1) & 8);
    const int noff = (lane & 8) ? 16 : 0;
    #pragma unroll
    for (int g = 0; g < 4; g++)
        ldsm4t(bh[g], b_s + (uint32_t)krow * G_BP + (uint32_t)(wn * 128 + g * 32) + noff);
    #pragma unroll
    for (int mt = 0; mt < 2; mt++)
        #pragma unroll
        for (int g = 0; g < 4; g++)
            #pragma unroll
            for (int s = 0; s < 2; s++)
                mma_f16(acc[mt][g * 2 + s], ah[mt], bh[g][s], bh[g][s + 2]);
}

// ---------------------------------------------------------------------------
// Fused prep: cvt hidden | cvt basic | transpose selfw | transpose rels.
// ---------------------------------------------------------------------------
#define NB_H    768
#define NB_BAS  2304
#define NB_SELF 576
#define NB_RELS 256

__global__ __launch_bounds__(256) void prep_kernel(
    const float* __restrict__ hidden, const float* __restrict__ basic,
    const float* __restrict__ selfw, const int* __restrict__ rels)
{
    const int blk = blockIdx.x;
    const int t = threadIdx.x;
    if (blk < NB_H + NB_BAS) {
        const float* src; __half* dst; int i;
        if (blk < NB_H) { src = hidden; dst = g_h; i = blk * 256 + t; }
        else            { src = basic;  dst = g_bas; i = (blk - NB_H) * 256 + t; }
        float4 v = reinterpret_cast<const float4*>(src)[i];
        reinterpret_cast<__half2*>(dst)[i * 2]     = __floats2half2_rn(v.x, v.y);
        reinterpret_cast<__half2*>(dst)[i * 2 + 1] = __floats2half2_rn(v.z, v.w);
    } else if (blk < NB_H + NB_BAS + NB_SELF) {
        __shared__ float tile[32][33];
        const int tl = blk - (NB_H + NB_BAS);
        const int h0 = (tl % 24) * 32, o0 = (tl / 24) * 32;
        const int tx = t & 31, ty = t >> 5;
        #pragma unroll
        for (int r = 0; r < 4; r++)
            tile[ty + 8 * r][tx] = selfw[(size_t)(o0 + ty + 8 * r) * H_ + h0 + tx];
        __syncthreads();
        #pragma unroll
        for (int r = 0; r < 4; r++)
            g_self[(size_t)(h0 + ty + 8 * r) * H_ + o0 + tx] =
                __float2half(tile[tx][ty + 8 * r]);
    } else {
        __shared__ int tile[32][33];
        const int id = blk - (NB_H + NB_BAS + NB_SELF);
        const int b = id >> 6, tl = id & 63;
        const int j0 = (tl & 7) * 32, i0 = (tl >> 3) * 32;
        const int tx = t & 31, ty = t >> 5;
        #pragma unroll
        for (int r = 0; r < 4; r++)
            tile[ty + 8 * r][tx] = rels[((size_t)b * S_ + i0 + ty + 8 * r) * S_ + j0 + tx];
        __syncthreads();
        #pragma unroll
        for (int r = 0; r < 4; r++)
            g_relsT[((size_t)b * S_ + j0 + ty + 8 * r) * S_ + i0 + tx] = tile[tx][ty + 8 * r];
    }
}

// ---------------------------------------------------------------------------
// build_w: histogram + W[b][i][c*256+j] fp16. All reads coalesced.
// ---------------------------------------------------------------------------
__global__ void build_w_kernel(const int* __restrict__ rels,
                               const float* __restrict__ rel_weight) {
    const int bi = blockIdx.x;
    const int b = bi >> 8;
    const int i = bi & 255;
    const int t = threadIdx.x;

    __shared__ int   cf[32], cr[32];
    __shared__ float inv_f[32], inv_r[32];
    __shared__ float rw[64 * 4];

    if (t < 32) { cf[t] = 0; cr[t] = 0; }
    rw[t] = rel_weight[t];
    __syncthreads();

    const int lf = rels[(b * S_ + i) * S_ + t];
    const int lr = g_relsT[(b * S_ + i) * S_ + t];
    if (lf > 0) atomicAdd(&cf[lf], 1);
    if (lr > 0) atomicAdd(&cr[lr], 1);
    __syncthreads();

    if (t < 32) {
        inv_f[t] = 1.0f / (float)(cf[t] > 0 ? cf[t] : 1);
        inv_r[t] = 1.0f / (float)(cr[t] > 0 ? cr[t] : 1);
    }
    __syncthreads();

    float w[4] = {0.f, 0.f, 0.f, 0.f};
    if (lf > 0) {
        const float s = inv_f[lf];
        #pragma unroll
        for (int c = 0; c < 4; c++) w[c] += rw[lf * 4 + c] * s;
    }
    if (lr > 0) {
        const float s = inv_r[lr];
        #pragma unroll
        for (int c = 0; c < 4; c++) w[c] += rw[(lr + 32) * 4 + c] * s;
    }
    #pragma unroll
    for (int c = 0; c < 4; c++)
        g_W[((size_t)(b * S_ + i)) * KW + c * 256 + t] = __float2half(w[c]);
}

// ---------------------------------------------------------------------------
// GEMM-HB: hb (1024x3840) = g_h (1024x768) @ [basic|selfT] (768x3840)
// grid (30, 16) = 480 CTAs, 128 thr, CTA 64x128, NC=24. One balanced wave.
// ---------------------------------------------------------------------------
__global__ __launch_bounds__(128, 4) void gemm_hb_kernel() {
    __shared__ __align__(128) char sm[3 * G_STG];
    const int n0 = blockIdx.x * 128;     // never straddles a 768-slot (768=6*128)
    const int m0 = blockIdx.y * 64;      // global row in [0,1024)
    const int cslot = n0 / 768;
    const int o0 = n0 - cslot * 768;

    const __half* A  = g_h + (size_t)m0 * H_;
    const __half* Bm = (cslot < 4) ? g_bas + (size_t)cslot * H_ * H_ + o0
                                   : g_self + o0;

    const int t = threadIdx.x, lane = t & 31, wid = t >> 5;
    const int wm = wid & 1, wn = wid >> 1;
    const uint32_t smb = s2u(sm);

    float acc[2][8][4] = {};
    const int NC = 24;
    #pragma unroll 1
    for (int p = 0; p < 2; p++) {
        const int k0 = p * 32;
        const uint32_t st = smb + (uint32_t)p * G_STG;
        ld_a32(A + k0, H_, st, t);
        ld_b32(Bm + (size_t)k0 * H_, H_, st + G_ABUF, t);
        asm volatile("cp.async.commit_group;" ::: "memory");
    }
    for (int c = 0; c < NC; c++) {
        asm volatile("cp.async.wait_group 1;" ::: "memory");
        __syncthreads();
        const uint32_t st = smb + (uint32_t)(c % 3) * G_STG;
        sub_t4(st, st + G_ABUF, acc, lane, wm, wn);
        sub_t4(st + 32, st + G_ABUF + 16 * G_BP, acc, lane, wm, wn);
        if (c + 2 < NC) {
            const int k0 = (c + 2) * 32;
            const uint32_t sn = smb + (uint32_t)((c + 2) % 3) * G_STG;
            ld_a32(A + k0, H_, sn, t);
            ld_b32(Bm + (size_t)k0 * H_, H_, sn + G_ABUF, t);
        }
        asm volatile("cp.async.commit_group;" ::: "memory");
    }

    #pragma unroll
    for (int mt = 0; mt < 2; mt++)
        #pragma unroll
        for (int nv = 0; nv < 8; nv++) {
            const int row = m0 + wm * 32 + mt * 16 + (lane >> 2);
            const int col = n0 + wn * 64 + nv * 8 + (lane & 3) * 2;
            *reinterpret_cast<__half2*>(g_hb + (size_t)row * NTOT + col) =
                __floats2half2_rn(acc[mt][nv][0], acc[mt][nv][1]);
            *reinterpret_cast<__half2*>(g_hb + (size_t)(row + 8) * NTOT + col) =
                __floats2half2_rn(acc[mt][nv][2], acc[mt][nv][3]);
        }
}

// ---------------------------------------------------------------------------
// GEMM-OUT split-K: part[kc] = W[:, kc*256:+256] @ hb-block (per batch)
// grid (6, 16, 4) = 384 CTAs, 128 thr, CTA 64x128, NC=8. One wave.
// ---------------------------------------------------------------------------
__global__ __launch_bounds__(128, 4) void gemm_out_kernel() {
    __shared__ __align__(128) char sm[3 * G_STG];
    const int n0 = blockIdx.x * 128;
    const int row0 = blockIdx.y * 64;        // global row in [0,1024)
    const int kc = blockIdx.z;
    const int b = row0 >> 8;

    const __half* A  = g_W + (size_t)row0 * KW + kc * 256;
    const __half* Bm = g_hb + (size_t)b * S_ * NTOT + kc * 768 + n0;  // ld = NTOT

    const int t = threadIdx.x, lane = t & 31, wid = t >> 5;
    const int wm = wid & 1, wn = wid >> 1;
    const uint32_t smb = s2u(sm);

    float acc[2][8][4] = {};
    const int NC = 8;
    #pragma unroll 1
    for (int p = 0; p < 2; p++) {
        const int k0 = p * 32;
        const uint32_t st = smb + (uint32_t)p * G_STG;
        ld_a32(A + k0, KW, st, t);
        ld_b32(Bm + (size_t)k0 * NTOT, NTOT, st + G_ABUF, t);
        asm volatile("cp.async.commit_group;" ::: "memory");
    }
    for (int c = 0; c < NC; c++) {
        asm volatile("cp.async.wait_group 1;" ::: "memory");
        __syncthreads();
        const uint32_t st = smb + (uint32_t)(c % 3) * G_STG;
        sub_t4(st, st + G_ABUF, acc, lane, wm, wn);
        sub_t4(st + 32, st + G_ABUF + 16 * G_BP, acc, lane, wm, wn);
        if (c + 2 < NC) {
            const int k0 = (c + 2) * 32;
            const uint32_t sn = smb + (uint32_t)((c + 2) % 3) * G_STG;
            ld_a32(A + k0, KW, sn, t);
            ld_b32(Bm + (size_t)k0 * NTOT, NTOT, sn + G_ABUF, t);
        }
        asm volatile("cp.async.commit_group;" ::: "memory");
    }

    float* part = g_part + (size_t)kc * (B_ * S_ * H_);
    #pragma unroll
    for (int mt = 0; mt < 2; mt++)
        #pragma unroll
        for (int nv = 0; nv < 8; nv++) {
            const int row = row0 + wm * 32 + mt * 16 + (lane >> 2);
            const int col = n0 + wn * 64 + nv * 8 + (lane & 3) * 2;
            float2 v0, v1;
            v0.x = acc[mt][nv][0]; v0.y = acc[mt][nv][1];
            v1.x = acc[mt][nv][2]; v1.y = acc[mt][nv][3];
            *reinterpret_cast<float2*>(part + (size_t)row * H_ + col) = v0;
            *reinterpret_cast<float2*>(part + (size_t)(row + 8) * H_ + col) = v1;
        }
}

// ---------------------------------------------------------------------------
// Reduce: out = p0+p1+p2+p3 + self_slot(hb[:,3072+n]). 768 blocks x 256 thr.
// ---------------------------------------------------------------------------
__global__ __launch_bounds__(256) void reduce_kernel(float* __restrict__ out) {
    const int i = blockIdx.x * 256 + threadIdx.x;   // float4 index
    const int row = (i * 4) / H_;
    const int col = (i * 4) % H_;
    float4 s = reinterpret_cast<const float4*>(g_part)[i];
    #pragma unroll
    for (int kc = 1; kc < 4; kc++) {
        float4 p = reinterpret_cast<const float4*>(g_part + (size_t)kc * (B_ * S_ * H_))[i];
        s.x += p.x; s.y += p.y; s.z += p.z; s.w += p.w;
    }
    const __half2* sh = reinterpret_cast<const __half2*>(
        g_hb + (size_t)row * NTOT + 3072 + col);
    float2 a = __half22float2(sh[0]);
    float2 bv = __half22float2(sh[1]);
    s.x += a.x; s.y += a.y; s.z += bv.x; s.w += bv.y;
    reinterpret_cast<float4*>(out)[i] = s;
}

// ---------------------------------------------------------------------------
extern "C" void kernel_launch(void* const* d_in, const int* in_sizes, int n_in,
                              void* d_out, int out_size) {
    const float* hidden     = (const float*)d_in[0]; // [4,256,768]
    const int*   rels       = (const int*)  d_in[1]; // [4,256,256]
    const float* basic      = (const float*)d_in[2]; // [4,768,768]
    const float* rel_weight = (const float*)d_in[3]; // [64,4]
    const float* self_w     = (const float*)d_in[4]; // [768,768] (out,in)
    float* out = (float*)d_out;                      // [4,256,768]

    prep_kernel<<<NB_H + NB_BAS + NB_SELF + NB_RELS, 256>>>(hidden, basic, self_w, rels);
    build_w_kernel<<<B_ * S_, 256>>>(rels, rel_weight);
    gemm_hb_kernel<<<dim3(NTOT / 128, (B_ * S_) / 64), 128>>>();
    gemm_out_kernel<<<dim3(H_ / 128, (B_ * S_) / 64, 4), 128>>>();
    reduce_kernel<<<(B_ * S_ * H_) / 4 / 256, 256>>>(out);
}

// round 10
// speedup vs baseline: 1.1634x; 1.0350x over previous
#include <cuda_runtime.h>
#include <cuda_fp16.h>
#include <cstdint>

#define B_   4
#define S_   256
#define H_   768
#define NTOT 3840   // 5*768 : 4 basis slots + self slot
#define KW   1024   // 4*256 : step-2 K (4 c-blocks of 256)

// ---------------- static device scratch -------------------------------------
__device__ __align__(256) __half g_h[B_ * S_ * H_];      // hidden fp16 [1024][768]
__device__ __align__(256) __half g_bas[4 * H_ * H_];     // basic fp16 [c][h][o]
__device__ __align__(256) __half g_self[H_ * H_];        // selfw^T fp16 [h][o]
__device__ __align__(256) __half g_W[B_ * S_ * KW];      // W [b][i][c*256+j]
__device__ __align__(256) __half g_hb[B_ * S_ * NTOT];   // hb [b][s][n] (slots 0-3 used)
__device__ __align__(256) int    g_relsT[B_ * S_ * S_];  // rels transposed

// ---------------- helpers ---------------------------------------------------
__device__ __forceinline__ uint32_t s2u(const void* p) {
    uint32_t a;
    asm("{ .reg .u64 t; cvta.to.shared.u64 t, %1; cvt.u32.u64 %0, t; }"
        : "=r"(a) : "l"(p));
    return a;
}
__device__ __forceinline__ void cp16(uint32_t dst, const void* src) {
    asm volatile("cp.async.cg.shared.global [%0], [%1], 16;"
                 :: "r"(dst), "l"(src) : "memory");
}
__device__ __forceinline__ void ldsm4(uint32_t* r, uint32_t addr) {
    asm volatile("ldmatrix.sync.aligned.m8n8.x4.shared.b16 {%0,%1,%2,%3}, [%4];"
                 : "=r"(r[0]), "=r"(r[1]), "=r"(r[2]), "=r"(r[3]) : "r"(addr));
}
__device__ __forceinline__ void ldsm4t(uint32_t* r, uint32_t addr) {
    asm volatile("ldmatrix.sync.aligned.m8n8.x4.trans.shared.b16 {%0,%1,%2,%3}, [%4];"
                 : "=r"(r[0]), "=r"(r[1]), "=r"(r[2]), "=r"(r[3]) : "r"(addr));
}
__device__ __forceinline__ void mma_f16(float* d, const uint32_t* a,
                                        uint32_t b0, uint32_t b1) {
    asm volatile("mma.sync.aligned.m16n8k16.row.col.f32.f16.f16.f32 "
                 "{%0,%1,%2,%3}, {%4,%5,%6,%7}, {%8,%9}, {%0,%1,%2,%3};"
                 : "+f"(d[0]), "+f"(d[1]), "+f"(d[2]), "+f"(d[3])
                 : "r"(a[0]), "r"(a[1]), "r"(a[2]), "r"(a[3]), "r"(b0), "r"(b1));
}

// ---------------- unified GEMM geometry --------------------------------------
// CTA tile 64(M) x 128(N), 128 threads = 4 warps, warp tile 32x64 (NG=4).
// K-chunk 32. A: pitch 80 (conflict-free ldsm). B: 32 k-rows, pitch 272
// (conflict-free trans ldsm).
#define A_PITCH 80
#define G_BP    272
#define G_ABUF  (64 * A_PITCH)              // 5120
#define G_BBUF  (32 * G_BP)                 // 8704
#define G_STG   (G_ABUF + G_BBUF)           // 13824

__device__ __forceinline__ void ld_a32(const __half* __restrict__ src, int ld,
                                       uint32_t s, int t) {
    #pragma unroll
    for (int u = 0; u < 2; u++) {
        const int id = t + 128 * u;
        const int r = id >> 2, seg = id & 3;
        cp16(s + r * A_PITCH + seg * 16, src + (size_t)r * ld + seg * 8);
    }
}
__device__ __forceinline__ void ld_b32(const __half* __restrict__ src, int ld,
                                       uint32_t s, int t) {
    #pragma unroll
    for (int u = 0; u < 4; u++) {
        const int id = t + 128 * u;
        const int k = id >> 4, q = id & 15;
        cp16(s + k * G_BP + q * 16, src + (size_t)k * ld + q * 8);
    }
}

// One 16-K sub-chunk. wm,wn in {0,1}; 64 n per warp.
__device__ __forceinline__ void sub_t4(uint32_t a_s, uint32_t b_s,
                                       float acc[2][8][4],
                                       int lane, int wm, int wn)
{
    const int arow = wm * 32 + (lane & 15);
    const uint32_t abase = a_s + (uint32_t)arow * A_PITCH + (uint32_t)(lane >> 4) * 16;
    uint32_t ah[2][4], bh[4][4];
    ldsm4(ah[0], abase);
    ldsm4(ah[1], abase + 16 * A_PITCH);
    const int krow = (lane & 7) | ((lane >> 1) & 8);
    const int noff = (lane & 8) ? 16 : 0;
    #pragma unroll
    for (int g = 0; g < 4; g++)
        ldsm4t(bh[g], b_s + (uint32_t)krow * G_BP + (uint32_t)(wn * 128 + g * 32) + noff);
    #pragma unroll
    for (int mt = 0; mt < 2; mt++)
        #pragma unroll
        for (int g = 0; g < 4; g++)
            #pragma unroll
            for (int s = 0; s < 2; s++)
                mma_f16(acc[mt][g * 2 + s], ah[mt], bh[g][s], bh[g][s + 2]);
}

// ---------------------------------------------------------------------------
// Fused prep: cvt hidden | cvt basic | transpose selfw | transpose rels.
// ---------------------------------------------------------------------------
#define NB_H    768
#define NB_BAS  2304
#define NB_SELF 576
#define NB_RELS 256

__global__ __launch_bounds__(256) void prep_kernel(
    const float* __restrict__ hidden, const float* __restrict__ basic,
    const float* __restrict__ selfw, const int* __restrict__ rels)
{
    const int blk = blockIdx.x;
    const int t = threadIdx.x;
    if (blk < NB_H + NB_BAS) {
        const float* src; __half* dst; int i;
        if (blk < NB_H) { src = hidden; dst = g_h; i = blk * 256 + t; }
        else            { src = basic;  dst = g_bas; i = (blk - NB_H) * 256 + t; }
        float4 v = reinterpret_cast<const float4*>(src)[i];
        reinterpret_cast<__half2*>(dst)[i * 2]     = __floats2half2_rn(v.x, v.y);
        reinterpret_cast<__half2*>(dst)[i * 2 + 1] = __floats2half2_rn(v.z, v.w);
    } else if (blk < NB_H + NB_BAS + NB_SELF) {
        __shared__ float tile[32][33];
        const int tl = blk - (NB_H + NB_BAS);
        const int h0 = (tl % 24) * 32, o0 = (tl / 24) * 32;
        const int tx = t & 31, ty = t >> 5;
        #pragma unroll
        for (int r = 0; r < 4; r++)
            tile[ty + 8 * r][tx] = selfw[(size_t)(o0 + ty + 8 * r) * H_ + h0 + tx];
        __syncthreads();
        #pragma unroll
        for (int r = 0; r < 4; r++)
            g_self[(size_t)(h0 + ty + 8 * r) * H_ + o0 + tx] =
                __float2half(tile[tx][ty + 8 * r]);
    } else {
        __shared__ int tile[32][33];
        const int id = blk - (NB_H + NB_BAS + NB_SELF);
        const int b = id >> 6, tl = id & 63;
        const int j0 = (tl & 7) * 32, i0 = (tl >> 3) * 32;
        const int tx = t & 31, ty = t >> 5;
        #pragma unroll
        for (int r = 0; r < 4; r++)
            tile[ty + 8 * r][tx] = rels[((size_t)b * S_ + i0 + ty + 8 * r) * S_ + j0 + tx];
        __syncthreads();
        #pragma unroll
        for (int r = 0; r < 4; r++)
            g_relsT[((size_t)b * S_ + j0 + ty + 8 * r) * S_ + i0 + tx] = tile[tx][ty + 8 * r];
    }
}

// ---------------------------------------------------------------------------
// build_w: histogram + W[b][i][c*256+j] fp16. All reads coalesced.
// ---------------------------------------------------------------------------
__global__ void build_w_kernel(const int* __restrict__ rels,
                               const float* __restrict__ rel_weight) {
    const int bi = blockIdx.x;
    const int b = bi >> 8;
    const int i = bi & 255;
    const int t = threadIdx.x;

    __shared__ int   cf[32], cr[32];
    __shared__ float inv_f[32], inv_r[32];
    __shared__ float rw[64 * 4];

    if (t < 32) { cf[t] = 0; cr[t] = 0; }
    rw[t] = rel_weight[t];
    __syncthreads();

    const int lf = rels[(b * S_ + i) * S_ + t];
    const int lr = g_relsT[(b * S_ + i) * S_ + t];
    if (lf > 0) atomicAdd(&cf[lf], 1);
    if (lr > 0) atomicAdd(&cr[lr], 1);
    __syncthreads();

    if (t < 32) {
        inv_f[t] = 1.0f / (float)(cf[t] > 0 ? cf[t] : 1);
        inv_r[t] = 1.0f / (float)(cr[t] > 0 ? cr[t] : 1);
    }
    __syncthreads();

    float w[4] = {0.f, 0.f, 0.f, 0.f};
    if (lf > 0) {
        const float s = inv_f[lf];
        #pragma unroll
        for (int c = 0; c < 4; c++) w[c] += rw[lf * 4 + c] * s;
    }
    if (lr > 0) {
        const float s = inv_r[lr];
        #pragma unroll
        for (int c = 0; c < 4; c++) w[c] += rw[(lr + 32) * 4 + c] * s;
    }
    #pragma unroll
    for (int c = 0; c < 4; c++)
        g_W[((size_t)(b * S_ + i)) * KW + c * 256 + t] = __float2half(w[c]);
}

// ---------------------------------------------------------------------------
// GEMM-HB: hb (1024x3840) = g_h (1024x768) @ [basic|selfT] (768x3840)
// grid (30, 16) = 480 CTAs, 128 thr, CTA 64x128, NC=24, 3-stage.
// cslot<4: write fp16 hb. cslot==4 (self term): write fp32 base of `out`.
// ---------------------------------------------------------------------------
__global__ __launch_bounds__(128, 4) void gemm_hb_kernel(float* __restrict__ out) {
    __shared__ __align__(128) char sm[3 * G_STG];
    const int n0 = blockIdx.x * 128;     // never straddles a 768-slot
    const int m0 = blockIdx.y * 64;      // global row in [0,1024)
    const int cslot = n0 / 768;
    const int o0 = n0 - cslot * 768;

    const __half* A  = g_h + (size_t)m0 * H_;
    const __half* Bm = (cslot < 4) ? g_bas + (size_t)cslot * H_ * H_ + o0
                                   : g_self + o0;

    const int t = threadIdx.x, lane = t & 31, wid = t >> 5;
    const int wm = wid & 1, wn = wid >> 1;
    const uint32_t smb = s2u(sm);

    float acc[2][8][4] = {};
    const int NC = 24;
    #pragma unroll 1
    for (int p = 0; p < 2; p++) {
        const int k0 = p * 32;
        const uint32_t st = smb + (uint32_t)p * G_STG;
        ld_a32(A + k0, H_, st, t);
        ld_b32(Bm + (size_t)k0 * H_, H_, st + G_ABUF, t);
        asm volatile("cp.async.commit_group;" ::: "memory");
    }
    for (int c = 0; c < NC; c++) {
        asm volatile("cp.async.wait_group 1;" ::: "memory");
        __syncthreads();
        const uint32_t st = smb + (uint32_t)(c % 3) * G_STG;
        sub_t4(st, st + G_ABUF, acc, lane, wm, wn);
        sub_t4(st + 32, st + G_ABUF + 16 * G_BP, acc, lane, wm, wn);
        if (c + 2 < NC) {
            const int k0 = (c + 2) * 32;
            const uint32_t sn = smb + (uint32_t)((c + 2) % 3) * G_STG;
            ld_a32(A + k0, H_, sn, t);
            ld_b32(Bm + (size_t)k0 * H_, H_, sn + G_ABUF, t);
        }
        asm volatile("cp.async.commit_group;" ::: "memory");
    }

    if (cslot < 4) {
        #pragma unroll
        for (int mt = 0; mt < 2; mt++)
            #pragma unroll
            for (int nv = 0; nv < 8; nv++) {
                const int row = m0 + wm * 32 + mt * 16 + (lane >> 2);
                const int col = n0 + wn * 64 + nv * 8 + (lane & 3) * 2;
                *reinterpret_cast<__half2*>(g_hb + (size_t)row * NTOT + col) =
                    __floats2half2_rn(acc[mt][nv][0], acc[mt][nv][1]);
                *reinterpret_cast<__half2*>(g_hb + (size_t)(row + 8) * NTOT + col) =
                    __floats2half2_rn(acc[mt][nv][2], acc[mt][nv][3]);
            }
    } else {
        #pragma unroll
        for (int mt = 0; mt < 2; mt++)
            #pragma unroll
            for (int nv = 0; nv < 8; nv++) {
                const int row = m0 + wm * 32 + mt * 16 + (lane >> 2);
                const int col = o0 + wn * 64 + nv * 8 + (lane & 3) * 2;
                float2 v0, v1;
                v0.x = acc[mt][nv][0]; v0.y = acc[mt][nv][1];
                v1.x = acc[mt][nv][2]; v1.y = acc[mt][nv][3];
                *reinterpret_cast<float2*>(out + (size_t)row * H_ + col) = v0;
                *reinterpret_cast<float2*>(out + (size_t)(row + 8) * H_ + col) = v1;
            }
    }
}

// ---------------------------------------------------------------------------
// GEMM-OUT split-K: out += W[:, kc*256:+256] @ hb-slot (per batch), via RED.
// grid (6, 16, 4) = 384 CTAs, 128 thr, CTA 64x128, NC=8, 4-stage (dyn smem).
// ---------------------------------------------------------------------------
#define OUT_SMEM (4 * G_STG)   // 55296

__global__ __launch_bounds__(128, 4) void gemm_out_kernel(float* __restrict__ out) {
    extern __shared__ __align__(128) char smo[];
    const int n0 = blockIdx.x * 128;
    const int row0 = blockIdx.y * 64;        // global row in [0,1024)
    const int kc = blockIdx.z;
    const int b = row0 >> 8;

    const __half* A  = g_W + (size_t)row0 * KW + kc * 256;
    const __half* Bm = g_hb + (size_t)b * S_ * NTOT + kc * 768 + n0;  // ld = NTOT

    const int t = threadIdx.x, lane = t & 31, wid = t >> 5;
    const int wm = wid & 1, wn = wid >> 1;
    const uint32_t smb = s2u(smo);

    float acc[2][8][4] = {};
    const int NC = 8;
    #pragma unroll 1
    for (int p = 0; p < 3; p++) {
        const int k0 = p * 32;
        const uint32_t st = smb + (uint32_t)p * G_STG;
        ld_a32(A + k0, KW, st, t);
        ld_b32(Bm + (size_t)k0 * NTOT, NTOT, st + G_ABUF, t);
        asm volatile("cp.async.commit_group;" ::: "memory");
    }
    for (int c = 0; c < NC; c++) {
        asm volatile("cp.async.wait_group 2;" ::: "memory");
        __syncthreads();
        const uint32_t st = smb + (uint32_t)(c & 3) * G_STG;
        sub_t4(st, st + G_ABUF, acc, lane, wm, wn);
        sub_t4(st + 32, st + G_ABUF + 16 * G_BP, acc, lane, wm, wn);
        if (c + 3 < NC) {
            const int k0 = (c + 3) * 32;
            const uint32_t sn = smb + (uint32_t)((c + 3) & 3) * G_STG;
            ld_a32(A + k0, KW, sn, t);
            ld_b32(Bm + (size_t)k0 * NTOT, NTOT, sn + G_ABUF, t);
        }
        asm volatile("cp.async.commit_group;" ::: "memory");
    }

    // epilogue: fire-and-forget global reductions onto the fp32 base.
    #pragma unroll
    for (int mt = 0; mt < 2; mt++)
        #pragma unroll
        for (int nv = 0; nv < 8; nv++) {
            const int row = row0 + wm * 32 + mt * 16 + (lane >> 2);
            const int col = n0 + wn * 64 + nv * 8 + (lane & 3) * 2;
            float* p0 = out + (size_t)row * H_ + col;
            float* p1 = out + (size_t)(row + 8) * H_ + col;
            atomicAdd(p0,     acc[mt][nv][0]);
            atomicAdd(p0 + 1, acc[mt][nv][1]);
            atomicAdd(p1,     acc[mt][nv][2]);
            atomicAdd(p1 + 1, acc[mt][nv][3]);
        }
}

// ---------------------------------------------------------------------------
extern "C" void kernel_launch(void* const* d_in, const int* in_sizes, int n_in,
                              void* d_out, int out_size) {
    const float* hidden     = (const float*)d_in[0]; // [4,256,768]
    const int*   rels       = (const int*)  d_in[1]; // [4,256,256]
    const float* basic      = (const float*)d_in[2]; // [4,768,768]
    const float* rel_weight = (const float*)d_in[3]; // [64,4]
    const float* self_w     = (const float*)d_in[4]; // [768,768] (out,in)
    float* out = (float*)d_out;                      // [4,256,768]

    cudaFuncSetAttribute(gemm_out_kernel,
                         cudaFuncAttributeMaxDynamicSharedMemorySize, OUT_SMEM);

    prep_kernel<<<NB_H + NB_BAS + NB_SELF + NB_RELS, 256>>>(hidden, basic, self_w, rels);
    build_w_kernel<<<B_ * S_, 256>>>(rels, rel_weight);
    gemm_hb_kernel<<<dim3(NTOT / 128, (B_ * S_) / 64), 128>>>(out);
    gemm_out_kernel<<<dim3(H_ / 128, (B_ * S_) / 64, 4), 128, OUT_SMEM>>>(out);
}